// round 7
// baseline (speedup 1.0000x reference)
#include <cuda_runtime.h>
#include <cstdint>
#include <math.h>

// ---- problem constants ----
#define BATCH    16
#define KTUP     16384
#define ADDS     32
#define NP       36          // 2^2 + 32 candidates per point
#define DIM      65536       // IN_DIM == OUT_DIM
#define HALF_B   8

// 4MB precomputed-parameter scratch: {m0, m1, nh, val} per (b, k)
__device__ float4 g_params[BATCH * KTUP];

// =====================================================================
// threefry-2x32, 20 rounds, exactly as jax._src.prng (key = (0, 42)).
// Partitionable mode: counter = (0, flat_index), bits = o0 ^ o1.
// =====================================================================
__device__ __forceinline__ void threefry2x32_42(uint32_t c0, uint32_t c1,
                                                uint32_t& o0, uint32_t& o1) {
    const uint32_t ks0 = 0u;
    const uint32_t ks1 = 42u;
    const uint32_t ks2 = 0x1BD11BDAu ^ 0u ^ 42u;
    uint32_t x0 = c0 + ks0;
    uint32_t x1 = c1 + ks1;
#define TF_R(rot) { x0 += x1; x1 = __funnelshift_l(x1, x1, rot); x1 ^= x0; }
    TF_R(13) TF_R(15) TF_R(26) TF_R(6)   x0 += ks1; x1 += ks2 + 1u;
    TF_R(17) TF_R(29) TF_R(16) TF_R(24)  x0 += ks2; x1 += ks0 + 2u;
    TF_R(13) TF_R(15) TF_R(26) TF_R(6)   x0 += ks0; x1 += ks1 + 3u;
    TF_R(17) TF_R(29) TF_R(16) TF_R(24)  x0 += ks1; x1 += ks2 + 4u;
    TF_R(13) TF_R(15) TF_R(26) TF_R(6)   x0 += ks2; x1 += ks0 + 5u;
#undef TF_R
    o0 = x0; o1 = x1;
}

__device__ __forceinline__ uint32_t jax_random_bits32(uint32_t e) {
    uint32_t o0, o1;
    threefry2x32_42(0u, e, o0, o1);
    return o0 ^ o1;
}

// bits -> uniform [0,1) -> *(1-1e-6) -> *65536 -> floor -> int32, bit-exact vs JAX
__device__ __forceinline__ int bits_to_idx(uint32_t bits) {
    float u = __uint_as_float((bits >> 9) | 0x3f800000u) - 1.0f;
    const float OME = (float)(1.0 - 1e-6);   // fl32(0.999999)
    float t = __fmul_rn(__fmul_rn(u, OME), 65536.0f);
    return (int)t;                           // trunc == floor, t >= 0
}

// ---- sigmoid / softplus: IDENTICAL arithmetic to passing rounds 4-6 ----
__device__ __forceinline__ float xla_sigmoid(float v) {
    float e = expf(-v);                      // accurate expf
    return __fdiv_rn(1.0f, __fadd_rn(1.0f, e));
}
__device__ __forceinline__ float softplus_f(float v) {
    return fmaxf(v, 0.0f) + log1pf(__expf(-fabsf(v)));
}

// =====================================================================
// prolog: blocks [0, 1024)    -> per-(b,k) parameter precompute
//         blocks [1024, 2048) -> y[b, o] = bias[o]  (float4)
// =====================================================================
__global__ __launch_bounds__(256) void hyper_prolog(const float4* __restrict__ res4,
                                                    const float4* __restrict__ bias4,
                                                    float4*       __restrict__ y4) {
    const int b = blockIdx.x;
    const int t = threadIdx.x;
    if (b < (BATCH * KTUP) / 256) {
        int i = b * 256 + t;                         // 0 .. BATCH*KTUP-1
        float4 r = __ldg(&res4[i]);
        float4 p;
        p.x = __fmul_rn(xla_sigmoid(r.x), 65535.0f); // m0
        p.y = __fmul_rn(xla_sigmoid(r.y), 65535.0f); // m1
        float sg = (softplus_f(r.z + 2.0f) + 1e-6f) * 65536.0f;
        p.z = -0.5f / (sg * sg);                     // nh
        p.w = r.w;                                   // val
        g_params[i] = p;
    } else {
        int i = (b - (BATCH * KTUP) / 256) * 256 + t;   // float4 element index
        y4[i] = __ldg(&bias4[i & (DIM / 4 - 1)]);
    }
}

// =====================================================================
// main: one warp per (b_half, k); lane = sample index a (0..31).
// dim1 (gather-index) hashes computed FIRST so both sample gathers are
// in flight under the remaining ~140 ALU instrs. Lanes 0..3 carry the 8
// floor/ceil neighbors merged by out-row; the two x-reads per batch are
// deduplicated across the lane pair via shfl (4 gathers total, was 8).
// =====================================================================
__global__ __launch_bounds__(256) void hyper_main(const float* __restrict__ x,
                                                  float*       __restrict__ y) {
    const uint32_t w    = blockIdx.x * 8u + (threadIdx.x >> 5);   // 0 .. 131071
    const uint32_t lane = threadIdx.x & 31u;
    const uint32_t bh   = w >> 14;           // 0..7
    const uint32_t k    = w & (KTUP - 1);

    // ---- precomputed params (warp-uniform broadcast loads) ----
    const float4 p0 = __ldg(&g_params[bh * KTUP + k]);            // batch bh
    const float4 p1 = __ldg(&g_params[(bh + HALF_B) * KTUP + k]); // batch bh+8

    const float* xr0 = x + (bh << 16);
    const float* xr1 = x + ((bh + HALF_B) << 16);
    float* yr0 = y + (bh << 16);
    float* yr1 = y + ((bh + HALF_B) << 16);

    // ---- dim1 (in-index) hashes first: get gathers airborne early ----
    const uint32_t e00 = w * (ADDS * 2) + lane * 2u;
    const int si1_0 = bits_to_idx(jax_random_bits32(e00 + 1u));          // (bh,   dim1)
    const float xs0 = __ldg(xr0 + si1_0);                                // gather #1
    const int si1_1 = bits_to_idx(jax_random_bits32(e00 + 0x800001u));   // (bh+8, dim1)
    const float xs1 = __ldg(xr1 + si1_1);                                // gather #2

    // ---- neighbor gathers (lanes 0..3), dedup'd across the lane pair ----
    float pa = 0.0f, pb = 0.0f, xf = 0.0f, xc = 0.0f;
    int   ng0 = 0;
    if (lane < 4) {
        const bool hb  = lane >= 2;                 // batch-half select
        const float mm0 = hb ? p1.x : p0.x;
        const float mm1 = hb ? p1.y : p0.y;
        const float nhh = hb ? p1.z : p0.z;
        const bool  cc  = (lane & 1);               // ceil-of-m0 corner?
        float g0  = cc ? ceilf(mm0) : floorf(mm0);
        float f1v = floorf(mm1), c1v = ceilf(mm1);
        ng0 = (int)g0;
        const int nf1 = (int)f1v, nc1 = (int)c1v;
        // lane even loads x[f1], lane odd loads x[c1]; exchange via shfl
        const float* xr = hb ? xr1 : xr0;
        float xown = __ldg(xr + (cc ? nc1 : nf1));
        float xoth = __shfl_xor_sync(0x0000000Fu, xown, 1);
        xf = cc ? xoth : xown;
        xc = cc ? xown : xoth;
        float d0 = g0 - mm0;
        float df = f1v - mm1, dc = c1v - mm1;
        pa = __expf(fmaf(d0, d0, df * df) * nhh);   // corner (g0, f1)
        pb = __expf(fmaf(d0, d0, dc * dc) * nhh);   // corner (g0, c1)
    }

    // ---- dim0 (out-index) hashes ----
    const int si0_0 = bits_to_idx(jax_random_bits32(e00));               // (bh,   dim0)
    const int si0_1 = bits_to_idx(jax_random_bits32(e00 + 0x800000u));   // (bh+8, dim0)

    // ---- Gaussian props for samples ----
    float d0 = (float)si0_0 - p0.x;
    float d1 = (float)si1_0 - p0.y;
    const float psamp0 = __expf(fmaf(d0, d0, d1 * d1) * p0.z);
    d0 = (float)si0_1 - p1.x;
    d1 = (float)si1_1 - p1.y;
    const float psamp1 = __expf(fmaf(d0, d0, d1 * d1) * p1.z);

    // ---- normalization: den = sum_p props + P*eps ----
    float s0 = psamp0 + ((lane < 2)              ? pa + pb : 0.0f);
    float s1 = psamp1 + ((lane >= 2 && lane < 4) ? pa + pb : 0.0f);
#pragma unroll
    for (int o = 16; o > 0; o >>= 1) {
        s0 += __shfl_xor_sync(0xffffffffu, s0, o);
        s1 += __shfl_xor_sync(0xffffffffu, s1, o);
    }
    const float sc0 = __fdividef(p0.w, s0 + (float)(NP) * 1e-6f);
    const float sc1 = __fdividef(p1.w, s1 + (float)(NP) * 1e-6f);

    // ---- scatter-add (terminal; no dependents) ----
    atomicAdd(yr0 + si0_0, sc0 * psamp0 * xs0);
    atomicAdd(yr1 + si0_1, sc1 * psamp1 * xs1);
    if (lane < 4) {
        float*      yr = (lane >= 2) ? yr1 : yr0;
        const float sc = (lane >= 2) ? sc1 : sc0;
        atomicAdd(yr + ng0, sc * fmaf(pa, xf, pb * xc));
    }
}

// =====================================================================
extern "C" void kernel_launch(void* const* d_in, const int* in_sizes, int n_in,
                              void* d_out, int out_size) {
    const float*  x     = (const float*)d_in[0];          // (16, 65536)
    const float4* res4  = (const float4*)d_in[1];         // (16, 16384, 4)
    const float4* bias4 = (const float4*)d_in[2];         // (65536,)
    // d_in[3] = temp_indices: fully overwritten by learn_cols -> unused
    float* y = (float*)d_out;                             // (16, 65536)

    const int nb_params = (BATCH * KTUP) / 256;           // 1024
    const int nb_init   = (BATCH * DIM / 4) / 256;        // 1024
    hyper_prolog<<<nb_params + nb_init, 256>>>(res4, bias4, (float4*)y);
    hyper_main<<<(HALF_B * KTUP) / 8, 256>>>(x, y);
}

// round 9
// speedup vs baseline: 1.0289x; 1.0289x over previous
#include <cuda_runtime.h>
#include <cstdint>
#include <math.h>

// ---- problem constants ----
#define BATCH    16
#define KTUP     16384
#define ADDS     32
#define NP       36          // 2^2 + 32 candidates per point
#define DIM      65536       // IN_DIM == OUT_DIM
#define HALF_B   8

// 4MB precomputed-parameter scratch: {m0, m1, nh, val} per (b, k)
__device__ float4 g_params[BATCH * KTUP];

// =====================================================================
// threefry-2x32, 20 rounds, exactly as jax._src.prng (key = (0, 42)).
// Partitionable mode: counter = (0, flat_index), bits = o0 ^ o1.
// =====================================================================
__device__ __forceinline__ void threefry2x32_42(uint32_t c0, uint32_t c1,
                                                uint32_t& o0, uint32_t& o1) {
    const uint32_t ks0 = 0u;
    const uint32_t ks1 = 42u;
    const uint32_t ks2 = 0x1BD11BDAu ^ 0u ^ 42u;
    uint32_t x0 = c0 + ks0;
    uint32_t x1 = c1 + ks1;
#define TF_R(rot) { x0 += x1; x1 = __funnelshift_l(x1, x1, rot); x1 ^= x0; }
    TF_R(13) TF_R(15) TF_R(26) TF_R(6)   x0 += ks1; x1 += ks2 + 1u;
    TF_R(17) TF_R(29) TF_R(16) TF_R(24)  x0 += ks2; x1 += ks0 + 2u;
    TF_R(13) TF_R(15) TF_R(26) TF_R(6)   x0 += ks0; x1 += ks1 + 3u;
    TF_R(17) TF_R(29) TF_R(16) TF_R(24)  x0 += ks1; x1 += ks2 + 4u;
    TF_R(13) TF_R(15) TF_R(26) TF_R(6)   x0 += ks2; x1 += ks0 + 5u;
#undef TF_R
    o0 = x0; o1 = x1;
}

__device__ __forceinline__ uint32_t jax_random_bits32(uint32_t e) {
    uint32_t o0, o1;
    threefry2x32_42(0u, e, o0, o1);
    return o0 ^ o1;
}

// bits -> uniform [0,1) -> *(1-1e-6) -> *65536 -> floor -> int32, bit-exact vs JAX
__device__ __forceinline__ int bits_to_idx(uint32_t bits) {
    float u = __uint_as_float((bits >> 9) | 0x3f800000u) - 1.0f;
    const float OME = (float)(1.0 - 1e-6);   // fl32(0.999999)
    float t = __fmul_rn(__fmul_rn(u, OME), 65536.0f);
    return (int)t;                           // trunc == floor, t >= 0
}

// ---- sigmoid / softplus: IDENTICAL arithmetic to passing rounds 4-7 ----
__device__ __forceinline__ float xla_sigmoid(float v) {
    float e = expf(-v);                      // accurate expf
    return __fdiv_rn(1.0f, __fadd_rn(1.0f, e));
}
__device__ __forceinline__ float softplus_f(float v) {
    return fmaxf(v, 0.0f) + log1pf(__expf(-fabsf(v)));
}

// Warp sum via integer redux (sm_80+; f32 redux does NOT exist on sm_103).
// Fixed point 2^24: sum of props <= 36 -> max 6.0e8 < 2^31, no overflow.
// Quantization <= 6e-8/term on a denominator >= 4 -> ~1e-7 relative; the
// denominator is a continuous quantity so the output moves ~1e-7.
#define FIXPT 16777216.0f
__device__ __forceinline__ float warp_sum_prop(float v) {
    uint32_t iv = __float2uint_rn(v * FIXPT);
    uint32_t r;
    asm volatile("redux.sync.add.u32 %0, %1, 0xffffffff;" : "=r"(r) : "r"(iv));
    return __uint2float_rn(r) * (1.0f / FIXPT);
}

// =====================================================================
// prolog: blocks [0, 1024)    -> per-(b,k) parameter precompute
//         blocks [1024, 2048) -> y[b, o] = bias[o]  (float4)
// =====================================================================
__global__ __launch_bounds__(256) void hyper_prolog(const float4* __restrict__ res4,
                                                    const float4* __restrict__ bias4,
                                                    float4*       __restrict__ y4) {
    const int b = blockIdx.x;
    const int t = threadIdx.x;
    if (b < (BATCH * KTUP) / 256) {
        int i = b * 256 + t;                         // 0 .. BATCH*KTUP-1
        float4 r = __ldg(&res4[i]);
        float4 p;
        p.x = __fmul_rn(xla_sigmoid(r.x), 65535.0f); // m0
        p.y = __fmul_rn(xla_sigmoid(r.y), 65535.0f); // m1
        float sg = (softplus_f(r.z + 2.0f) + 1e-6f) * 65536.0f;
        p.z = -0.5f / (sg * sg);                     // nh
        p.w = r.w;                                   // val
        g_params[i] = p;
    } else {
        int i = (b - (BATCH * KTUP) / 256) * 256 + t;   // float4 element index
        y4[i] = __ldg(&bias4[i & (DIM / 4 - 1)]);
    }
}

// =====================================================================
// main: one warp per (b_half, k); lane = sample index a (0..31).
// 4 partitionable-threefry hashes per lane: (bh, r=0/1), (bh+8, r=0/1).
// Lanes 0..3 carry the 8 floor/ceil neighbors merged by out-row; the two
// x-reads per (batch, out-row) pair are dedup'd across the lane pair via
// one shfl. Warp sums via redux.sync.add.u32 (fixed point).
// =====================================================================
__global__ __launch_bounds__(256, 8) void hyper_main(const float* __restrict__ x,
                                                     float*       __restrict__ y) {
    const uint32_t w    = blockIdx.x * 8u + (threadIdx.x >> 5);   // 0 .. 131071
    const uint32_t lane = threadIdx.x & 31u;
    const uint32_t bh   = w >> 14;           // 0..7
    const uint32_t k    = w & (KTUP - 1);

    // ---- precomputed params (warp-uniform broadcast loads) ----
    const float4 p0 = __ldg(&g_params[bh * KTUP + k]);            // batch bh
    const float4 p1 = __ldg(&g_params[(bh + HALF_B) * KTUP + k]); // batch bh+8

    // ---- sampled integer tuples: flat element index in (B,K,ADD,RANK) ----
    const uint32_t e00 = w * (ADDS * 2) + lane * 2u;
    int si0[2], si1[2];
    si0[0] = bits_to_idx(jax_random_bits32(e00));                 // (bh,   dim0)
    si1[0] = bits_to_idx(jax_random_bits32(e00 + 1u));            // (bh,   dim1)
    si0[1] = bits_to_idx(jax_random_bits32(e00 + 0x800000u));     // (bh+8, dim0)
    si1[1] = bits_to_idx(jax_random_bits32(e00 + 0x800001u));     // (bh+8, dim1)

    // ---- Gaussian props for samples ----
    float psamp[2];
    {
        float d0 = (float)si0[0] - p0.x;
        float d1 = (float)si1[0] - p0.y;
        psamp[0] = __expf(fmaf(d0, d0, d1 * d1) * p0.z);
        d0 = (float)si0[1] - p1.x;
        d1 = (float)si1[1] - p1.y;
        psamp[1] = __expf(fmaf(d0, d0, d1 * d1) * p1.z);
    }

    // ---- neighbors: lanes 0..3, two corners (one out-row) each ----
    float pa = 0.0f, pb = 0.0f;
    int   ng0 = 0, nf1 = 0, nc1 = 0;
    if (lane < 4) {
        const bool hb  = lane >= 2;                 // batch-half select
        const float mm0 = hb ? p1.x : p0.x;
        const float mm1 = hb ? p1.y : p0.y;
        const float nhh = hb ? p1.z : p0.z;
        float g0  = (lane & 1) ? ceilf(mm0) : floorf(mm0);
        float f1v = floorf(mm1), c1v = ceilf(mm1);
        ng0 = (int)g0;  nf1 = (int)f1v;  nc1 = (int)c1v;
        float d0 = g0 - mm0;
        float df = f1v - mm1, dc = c1v - mm1;
        pa = __expf(fmaf(d0, d0, df * df) * nhh);   // corner (g0, f1)
        pb = __expf(fmaf(d0, d0, dc * dc) * nhh);   // corner (g0, c1)
    }

    // ---- normalization: den = sum_p props + P*eps (integer redux) ----
    const float s0 = warp_sum_prop(psamp[0] + ((lane < 2)              ? pa + pb : 0.0f));
    const float s1 = warp_sum_prop(psamp[1] + ((lane >= 2 && lane < 4) ? pa + pb : 0.0f));
    const float sc0 = __fdividef(p0.w, s0 + (float)(NP) * 1e-6f);
    const float sc1 = __fdividef(p1.w, s1 + (float)(NP) * 1e-6f);

    // ---- gather / scatter-add ----
    const float* xr0 = x + (bh << 16);
    const float* xr1 = x + ((bh + HALF_B) << 16);
    float* yr0 = y + (bh << 16);
    float* yr1 = y + ((bh + HALF_B) << 16);

    atomicAdd(yr0 + si0[0], sc0 * psamp[0] * __ldg(xr0 + si1[0]));
    atomicAdd(yr1 + si0[1], sc1 * psamp[1] * __ldg(xr1 + si1[1]));
    if (lane < 4) {
        const bool hb = lane >= 2;
        const float* xr = hb ? xr1 : xr0;
        float*       yr = hb ? yr1 : yr0;
        const float  sc = hb ? sc1 : sc0;
        // lane-pair dedup: even lane loads x[f1], odd loads x[c1], exchange
        const bool cc = (lane & 1);
        float xown = __ldg(xr + (cc ? nc1 : nf1));
        float xoth = __shfl_xor_sync(0x0000000Fu, xown, 1);
        float xf = cc ? xoth : xown;
        float xc = cc ? xown : xoth;
        atomicAdd(yr + ng0, sc * fmaf(pa, xf, pb * xc));
    }
}

// =====================================================================
extern "C" void kernel_launch(void* const* d_in, const int* in_sizes, int n_in,
                              void* d_out, int out_size) {
    const float*  x     = (const float*)d_in[0];          // (16, 65536)
    const float4* res4  = (const float4*)d_in[1];         // (16, 16384, 4)
    const float4* bias4 = (const float4*)d_in[2];         // (65536,)
    // d_in[3] = temp_indices: fully overwritten by learn_cols -> unused
    float* y = (float*)d_out;                             // (16, 65536)

    const int nb_params = (BATCH * KTUP) / 256;           // 1024
    const int nb_init   = (BATCH * DIM / 4) / 256;        // 1024
    hyper_prolog<<<nb_params + nb_init, 256>>>(res4, bias4, (float4*)y);
    hyper_main<<<(HALF_B * KTUP) / 8, 256>>>(x, y);
}

// round 10
// speedup vs baseline: 1.0428x; 1.0135x over previous
#include <cuda_runtime.h>
#include <cstdint>
#include <math.h>

// ---- problem constants ----
#define BATCH    16
#define KTUP     16384
#define ADDS     32
#define NP       36          // 2^2 + 32 candidates per point
#define DIM      65536       // IN_DIM == OUT_DIM
#define HALF_B   8

// 4MB precomputed-parameter scratch: {m0, m1, nh, val} per (b, k)
__device__ float4 g_params[BATCH * KTUP];

// =====================================================================
// threefry-2x32, 20 rounds, exactly as jax._src.prng (key = (0, 42)).
// Partitionable mode: counter = (0, flat_index), bits = o0 ^ o1.
// =====================================================================
__device__ __forceinline__ void threefry2x32_42(uint32_t c0, uint32_t c1,
                                                uint32_t& o0, uint32_t& o1) {
    const uint32_t ks0 = 0u;
    const uint32_t ks1 = 42u;
    const uint32_t ks2 = 0x1BD11BDAu ^ 0u ^ 42u;
    uint32_t x0 = c0 + ks0;
    uint32_t x1 = c1 + ks1;
#define TF_R(rot) { x0 += x1; x1 = __funnelshift_l(x1, x1, rot); x1 ^= x0; }
    TF_R(13) TF_R(15) TF_R(26) TF_R(6)   x0 += ks1; x1 += ks2 + 1u;
    TF_R(17) TF_R(29) TF_R(16) TF_R(24)  x0 += ks2; x1 += ks0 + 2u;
    TF_R(13) TF_R(15) TF_R(26) TF_R(6)   x0 += ks0; x1 += ks1 + 3u;
    TF_R(17) TF_R(29) TF_R(16) TF_R(24)  x0 += ks1; x1 += ks2 + 4u;
    TF_R(13) TF_R(15) TF_R(26) TF_R(6)   x0 += ks2; x1 += ks0 + 5u;
#undef TF_R
    o0 = x0; o1 = x1;
}

__device__ __forceinline__ uint32_t jax_random_bits32(uint32_t e) {
    uint32_t o0, o1;
    threefry2x32_42(0u, e, o0, o1);
    return o0 ^ o1;
}

// bits -> JAX index, bit-exact, 1 FFMA:
//   v = as_float((bits>>9)|0x3f800000) in [1,2);  u = v-1 exact (Sterbenz).
//   C = fl32(0.999999)*65536 is exponent-exact, and round(z)*2^16 ==
//   round(z*2^16), so round((v-1)*C) == round((v-1)*OME)*65536 == JAX's t.
__device__ __forceinline__ int bits_to_idx(uint32_t bits) {
    const float C = 0.999999f * 65536.0f;    // exact scale of fl32(0.999999)
    float v = __uint_as_float((bits >> 9) | 0x3f800000u);
    return (int)__fmaf_rn(v, C, -C);         // trunc == floor, arg >= 0
}

// ---- sigmoid / softplus: IDENTICAL arithmetic to passing rounds 4-9 ----
__device__ __forceinline__ float xla_sigmoid(float v) {
    float e = expf(-v);                      // accurate expf
    return __fdiv_rn(1.0f, __fadd_rn(1.0f, e));
}
__device__ __forceinline__ float softplus_f(float v) {
    return fmaxf(v, 0.0f) + log1pf(__expf(-fabsf(v)));
}

// Warp sum via integer redux (f32 redux does not exist on sm_103).
// Fixed point 2^24: sum <= 36 -> max 6.0e8 < 2^31. Validated in round 9.
#define FIXPT 16777216.0f
__device__ __forceinline__ float warp_sum_prop(float v) {
    uint32_t iv = __float2uint_rn(v * FIXPT);
    uint32_t r;
    asm volatile("redux.sync.add.u32 %0, %1, 0xffffffff;" : "=r"(r) : "r"(iv));
    return __uint2float_rn(r) * (1.0f / FIXPT);
}

// =====================================================================
// prolog: blocks [0, 512)    -> params, 2 elements/thread (ILP x2: the
//                               expf/div/log1p chains are latency-bound)
//         blocks [512, 1536) -> y[b, o] = bias[o]  (float4)
// =====================================================================
__global__ __launch_bounds__(256) void hyper_prolog(const float4* __restrict__ res4,
                                                    const float4* __restrict__ bias4,
                                                    float4*       __restrict__ y4) {
    const int b = blockIdx.x;
    const int t = threadIdx.x;
    if (b < 512) {
        const int i1 = b * 256 + t;                  // first half
        const int i2 = i1 + (BATCH * KTUP) / 2;      // second half
        float4 r1 = __ldg(&res4[i1]);
        float4 r2 = __ldg(&res4[i2]);
        float4 p1, p2;
        p1.x = __fmul_rn(xla_sigmoid(r1.x), 65535.0f);
        p2.x = __fmul_rn(xla_sigmoid(r2.x), 65535.0f);
        p1.y = __fmul_rn(xla_sigmoid(r1.y), 65535.0f);
        p2.y = __fmul_rn(xla_sigmoid(r2.y), 65535.0f);
        float sg1 = (softplus_f(r1.z + 2.0f) + 1e-6f) * 65536.0f;
        float sg2 = (softplus_f(r2.z + 2.0f) + 1e-6f) * 65536.0f;
        p1.z = -0.5f / (sg1 * sg1);
        p2.z = -0.5f / (sg2 * sg2);
        p1.w = r1.w;
        p2.w = r2.w;
        g_params[i1] = p1;
        g_params[i2] = p2;
    } else {
        int i = (b - 512) * 256 + t;                 // float4 element index
        y4[i] = __ldg(&bias4[i & (DIM / 4 - 1)]);
    }
}

// =====================================================================
// main (PDL secondary): hash phase runs BEFORE cudaGridDependencySynchronize,
// overlapping the prolog. Everything touching g_params / y comes after.
// =====================================================================
__global__ __launch_bounds__(256, 8) void hyper_main(const float* __restrict__ x,
                                                     float*       __restrict__ y) {
    const uint32_t w    = blockIdx.x * 8u + (threadIdx.x >> 5);   // 0 .. 131071
    const uint32_t lane = threadIdx.x & 31u;
    const uint32_t bh   = w >> 14;           // 0..7
    const uint32_t k    = w & (KTUP - 1);

    // ---- hash phase (independent of prolog) ----
    const uint32_t e00 = w * (ADDS * 2) + lane * 2u;
    int si0[2], si1[2];
    si0[0] = bits_to_idx(jax_random_bits32(e00));                 // (bh,   dim0)
    si1[0] = bits_to_idx(jax_random_bits32(e00 + 1u));            // (bh,   dim1)
    si0[1] = bits_to_idx(jax_random_bits32(e00 + 0x800000u));     // (bh+8, dim0)
    si1[1] = bits_to_idx(jax_random_bits32(e00 + 0x800001u));     // (bh+8, dim1)

    // ---- wait for prolog (params + y-init) ----
    cudaGridDependencySynchronize();

    // ---- precomputed params (warp-uniform broadcast loads) ----
    const float4 p0 = __ldg(&g_params[bh * KTUP + k]);            // batch bh
    const float4 p1 = __ldg(&g_params[(bh + HALF_B) * KTUP + k]); // batch bh+8

    // ---- Gaussian props for samples ----
    float psamp[2];
    {
        float d0 = (float)si0[0] - p0.x;
        float d1 = (float)si1[0] - p0.y;
        psamp[0] = __expf(fmaf(d0, d0, d1 * d1) * p0.z);
        d0 = (float)si0[1] - p1.x;
        d1 = (float)si1[1] - p1.y;
        psamp[1] = __expf(fmaf(d0, d0, d1 * d1) * p1.z);
    }

    // ---- neighbors: lanes 0..3, two corners (one out-row) each ----
    float pa = 0.0f, pb = 0.0f;
    int   ng0 = 0, nf1 = 0, nc1 = 0;
    if (lane < 4) {
        const bool hb  = lane >= 2;                 // batch-half select
        const float mm0 = hb ? p1.x : p0.x;
        const float mm1 = hb ? p1.y : p0.y;
        const float nhh = hb ? p1.z : p0.z;
        float g0  = (lane & 1) ? ceilf(mm0) : floorf(mm0);
        float f1v = floorf(mm1), c1v = ceilf(mm1);
        ng0 = (int)g0;  nf1 = (int)f1v;  nc1 = (int)c1v;
        float d0 = g0 - mm0;
        float df = f1v - mm1, dc = c1v - mm1;
        pa = __expf(fmaf(d0, d0, df * df) * nhh);   // corner (g0, f1)
        pb = __expf(fmaf(d0, d0, dc * dc) * nhh);   // corner (g0, c1)
    }

    // ---- normalization: den = sum_p props + P*eps (integer redux) ----
    const float s0 = warp_sum_prop(psamp[0] + ((lane < 2)              ? pa + pb : 0.0f));
    const float s1 = warp_sum_prop(psamp[1] + ((lane >= 2 && lane < 4) ? pa + pb : 0.0f));
    const float sc0 = __fdividef(p0.w, s0 + (float)(NP) * 1e-6f);
    const float sc1 = __fdividef(p1.w, s1 + (float)(NP) * 1e-6f);

    // ---- gather / scatter-add ----
    const float* xr0 = x + (bh << 16);
    const float* xr1 = x + ((bh + HALF_B) << 16);
    float* yr0 = y + (bh << 16);
    float* yr1 = y + ((bh + HALF_B) << 16);

    atomicAdd(yr0 + si0[0], sc0 * psamp[0] * __ldg(xr0 + si1[0]));
    atomicAdd(yr1 + si0[1], sc1 * psamp[1] * __ldg(xr1 + si1[1]));
    if (lane < 4) {
        const bool hb = lane >= 2;
        const float* xr = hb ? xr1 : xr0;
        float*       yr = hb ? yr1 : yr0;
        const float  sc = hb ? sc1 : sc0;
        // lane-pair dedup: even lane loads x[f1], odd loads x[c1], exchange
        const bool cc = (lane & 1);
        float xown = __ldg(xr + (cc ? nc1 : nf1));
        float xoth = __shfl_xor_sync(0x0000000Fu, xown, 1);
        float xf = cc ? xoth : xown;
        float xc = cc ? xown : xoth;
        atomicAdd(yr + ng0, sc * fmaf(pa, xf, pb * xc));
    }
}

// =====================================================================
extern "C" void kernel_launch(void* const* d_in, const int* in_sizes, int n_in,
                              void* d_out, int out_size) {
    const float*  x     = (const float*)d_in[0];          // (16, 65536)
    const float4* res4  = (const float4*)d_in[1];         // (16, 16384, 4)
    const float4* bias4 = (const float4*)d_in[2];         // (65536,)
    // d_in[3] = temp_indices: fully overwritten by learn_cols -> unused
    float* y = (float*)d_out;                             // (16, 65536)

    hyper_prolog<<<1536, 256>>>(res4, bias4, (float4*)y);

    // PDL: main may start early; it self-synchronizes via
    // cudaGridDependencySynchronize() before touching prolog outputs.
    cudaLaunchConfig_t cfg = {};
    cfg.gridDim       = dim3((HALF_B * KTUP) / 8);
    cfg.blockDim      = dim3(256);
    cfg.dynamicSmemBytes = 0;
    cfg.stream        = 0;
    cudaLaunchAttribute attrs[1];
    attrs[0].id = cudaLaunchAttributeProgrammaticStreamSerialization;
    attrs[0].val.programmaticStreamSerializationAllowed = 1;
    cfg.attrs   = attrs;
    cfg.numAttrs = 1;
    cudaLaunchKernelEx(&cfg, hyper_main, x, (float*)y);
}